// round 8
// baseline (speedup 1.0000x reference)
#include <cuda_runtime.h>
#include <cuda_bf16.h>
#include <cstdint>

// ---------------- problem-size constants (fixed by the dataset) -------------
#define MAXN 100000
#define MAXE 1600000

// ---------------- device scratch (allocation-free rule: __device__ globals) -
__device__ __align__(16) float g_Y [MAXN * 192];   // [y1 | y2 | y0] after GEMM1
__device__ __align__(16) float g_U [MAXN * 64];    // u = y1 + 2*L y2
__device__ __align__(16) float g_H2[MAXN * 192];   // [h1 | t1 | t2] for layer 2
__device__ __align__(16) float g_H3[MAXN * 384];   // [h2 | t1 | t2] for layer 3
__device__ __align__(16) float g_Wcat[128 * 192];  // [W1_1 | W1_2 | W1_0 - W1_2]

__device__ float g_dinv[MAXN];
__device__ int   g_deg [MAXN];
__device__ int   g_cnt [MAXN];
__device__ int   g_cur [MAXN];
__device__ int   g_rowstart[MAXN];
__device__ int   g_blocksums[256];
__device__ int   g_csr_src[MAXE];
__device__ float g_csr_w [MAXE];
__device__ int   g_is64;          // 1 if edge_index is int64, 0 if int32

// ---------------- packed f32x2 helpers (sm_103a) ----------------------------
__device__ __forceinline__ unsigned long long pack2(float x, float y) {
    unsigned long long r;
    asm("mov.b64 %0, {%1, %2};" : "=l"(r) : "f"(x), "f"(y));
    return r;
}
__device__ __forceinline__ float2 unpack2(unsigned long long v) {
    float2 r;
    asm("mov.b64 {%0, %1}, %2;" : "=f"(r.x), "=f"(r.y) : "l"(v));
    return r;
}
__device__ __forceinline__ void fma2(unsigned long long& d,
                                     unsigned long long a,
                                     unsigned long long b) {
    asm("fma.rn.f32x2 %0, %1, %2, %3;" : "=l"(d) : "l"(a), "l"(b), "l"(d));
}

// ---------------- edge dtype detection + access -----------------------------
__device__ __forceinline__ void load_edge(const void* ei, int e, int E, int is64,
                                          int& s, int& d) {
    if (is64) {
        const long long* p = (const long long*)ei;
        s = (int)p[e];
        d = (int)p[E + e];
    } else {
        const int* p = (const int*)ei;
        s = p[e];
        d = p[E + e];
    }
}

// ---------------- setup kernels ---------------------------------------------
// init + dtype detection (thread 0)
__global__ void init_kernel(const int* __restrict__ ei32, int E, int N) {
    int i = blockIdx.x * blockDim.x + threadIdx.x;
    if (i < N) { g_deg[i] = 0; g_cnt[i] = 0; g_cur[i] = 0; }
    if (i == 0) {
        int is64 = 1;
        int nchk = (E < 64) ? E : 64;
        for (int j = 0; j < nchk; j++) {
            if (ei32[2 * j + 1] != 0) { is64 = 0; break; }
        }
        g_is64 = is64;
    }
}

__global__ void deg_cnt_kernel(const void* __restrict__ ei, int E) {
    int e = blockIdx.x * blockDim.x + threadIdx.x;
    if (e >= E) return;
    int is64 = g_is64;
    int s, d;
    load_edge(ei, e, E, is64, s, d);
    if (s != d) {
        atomicAdd(&g_deg[s], 1);
        atomicAdd(&g_cnt[d], 1);
    }
}

// scan over cnt (+ dinv from deg, fused)
__global__ void scan1_kernel(int N) {
    __shared__ int sm[1024];
    int t = threadIdx.x;
    int i = blockIdx.x * 1024 + t;
    if (i < N) {
        int dg = g_deg[i];
        g_dinv[i] = (dg > 0) ? rsqrtf((float)dg) : 0.0f;
    }
    int v = (i < N) ? g_cnt[i] : 0;
    sm[t] = v;
    __syncthreads();
    for (int off = 1; off < 1024; off <<= 1) {
        int x = (t >= off) ? sm[t - off] : 0;
        __syncthreads();
        sm[t] += x;
        __syncthreads();
    }
    if (i < N) g_rowstart[i] = sm[t] - v;
    if (t == 1023) g_blocksums[blockIdx.x] = sm[1023];
}

// parallel exclusive scan of block sums (nb <= 256)
__global__ void scan2_kernel(int nb) {
    __shared__ int sm[256];
    int t = threadIdx.x;
    int v = (t < nb) ? g_blocksums[t] : 0;
    sm[t] = v;
    __syncthreads();
    for (int off = 1; off < 256; off <<= 1) {
        int x = (t >= off) ? sm[t - off] : 0;
        __syncthreads();
        sm[t] += x;
        __syncthreads();
    }
    if (t < nb) g_blocksums[t] = sm[t] - v;
}

__global__ void scan3_kernel(int N) {
    int i = blockIdx.x * 1024 + threadIdx.x;
    if (i < N) g_rowstart[i] += g_blocksums[blockIdx.x];
}

__global__ void fill_kernel(const void* __restrict__ ei, int E) {
    int e = blockIdx.x * blockDim.x + threadIdx.x;
    if (e >= E) return;
    int is64 = g_is64;
    int s, d;
    load_edge(ei, e, E, is64, s, d);
    if (s != d) {
        float w = -g_dinv[s] * g_dinv[d];
        int p = g_rowstart[d] + atomicAdd(&g_cur[d], 1);
        g_csr_src[p] = s;
        g_csr_w[p]   = w;
    }
}

// Wcat = [W1[1] | W1[2] | W1[0]-W1[2]]   (128 x 192)
__global__ void wcat_kernel(const float* __restrict__ W1, float* __restrict__ Wc) {
    int idx = blockIdx.x * blockDim.x + threadIdx.x;
    if (idx >= 128 * 192) return;
    int i = idx / 192, j = idx % 192;
    float v;
    if (j < 64)        v = W1[8192     + i * 64 + j];
    else if (j < 128)  v = W1[2 * 8192 + i * 64 + (j - 64)];
    else               v = W1[           i * 64 + (j - 128)]
                         - W1[2 * 8192 + i * 64 + (j - 128)];
    Wc[idx] = v;
}

// ---------------- GEMM 128x64 (8x4 micro-tile) — used for N=192 (GEMM1) -----
__global__ __launch_bounds__(256) void gemm_kernel(
    const float* __restrict__ A, int lda,
    const float* __restrict__ B, int ldb,
    float* __restrict__ C, int ldc,
    int M, int N, int K,
    const float* __restrict__ bias, int do_relu)
{
    __shared__ __align__(16) float As[32][132];
    __shared__ __align__(16) unsigned long long Bsd[32][64];

    int tid = threadIdx.x;
    int tx = tid & 15;
    int ty = tid >> 4;
    int m0 = blockIdx.y * 128;
    int n0 = blockIdx.x * 64;

    unsigned long long acc[4][4];
#pragma unroll
    for (int i = 0; i < 4; i++)
#pragma unroll
        for (int j = 0; j < 4; j++) acc[i][j] = 0ull;

    for (int kt = 0; kt < K; kt += 32) {
#pragma unroll
        for (int i = 0; i < 4; i++) {
            int f = tid + i * 256;
            int m = f >> 3;
            int kk = (f & 7) << 2;
            float4 v = make_float4(0.f, 0.f, 0.f, 0.f);
            int row = m0 + m;
            if (row < M)
                v = *reinterpret_cast<const float4*>(A + (size_t)row * lda + kt + kk);
            As[kk + 0][m] = v.x;
            As[kk + 1][m] = v.y;
            As[kk + 2][m] = v.z;
            As[kk + 3][m] = v.w;
        }
#pragma unroll
        for (int i = 0; i < 2; i++) {
            int f = tid + i * 256;
            int k = f >> 4;
            int nn = (f & 15) << 2;
            float4 v = *reinterpret_cast<const float4*>(B + (size_t)(kt + k) * ldb + n0 + nn);
            Bsd[k][nn + 0] = pack2(v.x, v.x);
            Bsd[k][nn + 1] = pack2(v.y, v.y);
            Bsd[k][nn + 2] = pack2(v.z, v.z);
            Bsd[k][nn + 3] = pack2(v.w, v.w);
        }
        __syncthreads();
#pragma unroll
        for (int k = 0; k < 32; k++) {
            ulonglong2 a01 = *reinterpret_cast<const ulonglong2*>(&As[k][ty << 3]);
            ulonglong2 a23 = *reinterpret_cast<const ulonglong2*>(&As[k][(ty << 3) + 4]);
            ulonglong2 b01 = *reinterpret_cast<const ulonglong2*>(&Bsd[k][tx << 2]);
            ulonglong2 b23 = *reinterpret_cast<const ulonglong2*>(&Bsd[k][(tx << 2) + 2]);
            unsigned long long ar[4] = {a01.x, a01.y, a23.x, a23.y};
            unsigned long long br[4] = {b01.x, b01.y, b23.x, b23.y};
#pragma unroll
            for (int i = 0; i < 4; i++)
#pragma unroll
                for (int j = 0; j < 4; j++)
                    fma2(acc[i][j], ar[i], br[j]);
        }
        __syncthreads();
    }

    float bb[4];
#pragma unroll
    for (int j = 0; j < 4; j++)
        bb[j] = bias ? bias[n0 + (tx << 2) + j] : 0.f;

#pragma unroll
    for (int i = 0; i < 4; i++) {
        int row = m0 + (ty << 3) + 2 * i;
        float4 lo4, hi4;
        float* lop = &lo4.x;
        float* hip = &hi4.x;
#pragma unroll
        for (int j = 0; j < 4; j++) {
            float2 v = unpack2(acc[i][j]);
            float a = v.x + bb[j];
            float b = v.y + bb[j];
            if (do_relu) { a = fmaxf(a, 0.f); b = fmaxf(b, 0.f); }
            lop[j] = a;
            hip[j] = b;
        }
        if (row < M)
            *reinterpret_cast<float4*>(C + (size_t)row * ldc + n0 + (tx << 2)) = lo4;
        if (row + 1 < M)
            *reinterpret_cast<float4*>(C + (size_t)(row + 1) * ldc + n0 + (tx << 2)) = hi4;
    }
}

// ---------------- GEMM 128x128 (8x8 micro-tile, BK=16) — GEMM2/GEMM3 --------
// 32 FFMA2 per 6 LDS.128 per k per thread: FMA-issue-bound.
// Requires N % 128 == 0, K % 16 == 0.
__global__ __launch_bounds__(256) void gemm128_kernel(
    const float* __restrict__ A, int lda,
    const float* __restrict__ B, int ldb,
    float* __restrict__ C, int ldc,
    int M, int K,
    const float* __restrict__ bias, int do_relu)
{
    __shared__ __align__(16) float As[16][132];              // 8448 B
    __shared__ __align__(16) unsigned long long Bsd[16][128]; // 16384 B

    int tid = threadIdx.x;
    int tx = tid & 15;        // col group: cols tx*8 .. +7
    int ty = tid >> 4;        // row group: rows ty*8 .. +7
    int m0 = blockIdx.y * 128;
    int n0 = blockIdx.x * 128;

    unsigned long long acc[4][8];
#pragma unroll
    for (int i = 0; i < 4; i++)
#pragma unroll
        for (int j = 0; j < 8; j++) acc[i][j] = 0ull;

    for (int kt = 0; kt < K; kt += 16) {
        // A tile 128x16: 512 float4 loads, store transposed
#pragma unroll
        for (int i = 0; i < 2; i++) {
            int f = tid + i * 256;
            int m = f >> 2;
            int kk = (f & 3) << 2;
            float4 v = make_float4(0.f, 0.f, 0.f, 0.f);
            int row = m0 + m;
            if (row < M)
                v = *reinterpret_cast<const float4*>(A + (size_t)row * lda + kt + kk);
            As[kk + 0][m] = v.x;
            As[kk + 1][m] = v.y;
            As[kk + 2][m] = v.z;
            As[kk + 3][m] = v.w;
        }
        // B tile 16x128: duplicate {b,b}
#pragma unroll
        for (int i = 0; i < 2; i++) {
            int f = tid + i * 256;
            int k = f >> 5;
            int nn = (f & 31) << 2;
            float4 v = *reinterpret_cast<const float4*>(B + (size_t)(kt + k) * ldb + n0 + nn);
            Bsd[k][nn + 0] = pack2(v.x, v.x);
            Bsd[k][nn + 1] = pack2(v.y, v.y);
            Bsd[k][nn + 2] = pack2(v.z, v.z);
            Bsd[k][nn + 3] = pack2(v.w, v.w);
        }
        __syncthreads();
#pragma unroll
        for (int k = 0; k < 16; k++) {
            ulonglong2 a01 = *reinterpret_cast<const ulonglong2*>(&As[k][ty << 3]);
            ulonglong2 a23 = *reinterpret_cast<const ulonglong2*>(&As[k][(ty << 3) + 4]);
            ulonglong2 b01 = *reinterpret_cast<const ulonglong2*>(&Bsd[k][tx << 3]);
            ulonglong2 b23 = *reinterpret_cast<const ulonglong2*>(&Bsd[k][(tx << 3) + 2]);
            ulonglong2 b45 = *reinterpret_cast<const ulonglong2*>(&Bsd[k][(tx << 3) + 4]);
            ulonglong2 b67 = *reinterpret_cast<const ulonglong2*>(&Bsd[k][(tx << 3) + 6]);
            unsigned long long ar[4] = {a01.x, a01.y, a23.x, a23.y};
            unsigned long long br[8] = {b01.x, b01.y, b23.x, b23.y,
                                        b45.x, b45.y, b67.x, b67.y};
#pragma unroll
            for (int i = 0; i < 4; i++)
#pragma unroll
                for (int j = 0; j < 8; j++)
                    fma2(acc[i][j], ar[i], br[j]);
        }
        __syncthreads();
    }

    float bb[8];
#pragma unroll
    for (int j = 0; j < 8; j++)
        bb[j] = bias ? bias[n0 + (tx << 3) + j] : 0.f;

#pragma unroll
    for (int i = 0; i < 4; i++) {
        int row = m0 + (ty << 3) + 2 * i;
        float lo[8], hi[8];
#pragma unroll
        for (int j = 0; j < 8; j++) {
            float2 v = unpack2(acc[i][j]);
            float a = v.x + bb[j];
            float b = v.y + bb[j];
            if (do_relu) { a = fmaxf(a, 0.f); b = fmaxf(b, 0.f); }
            lo[j] = a;
            hi[j] = b;
        }
        if (row < M) {
            float* p = C + (size_t)row * ldc + n0 + (tx << 3);
            *reinterpret_cast<float4*>(p)     = make_float4(lo[0], lo[1], lo[2], lo[3]);
            *reinterpret_cast<float4*>(p + 4) = make_float4(lo[4], lo[5], lo[6], lo[7]);
        }
        if (row + 1 < M) {
            float* p = C + (size_t)(row + 1) * ldc + n0 + (tx << 3);
            *reinterpret_cast<float4*>(p)     = make_float4(hi[0], hi[1], hi[2], hi[3]);
            *reinterpret_cast<float4*>(p + 4) = make_float4(hi[4], hi[5], hi[6], hi[7]);
        }
    }
}

// ---------------- propagation: out = alpha*(L @ in) + beta*add + bias, relu -
__device__ __forceinline__ void accum4(float* acc, const float* p, float w) {
    float4 r = *reinterpret_cast<const float4*>(p);
    acc[0] = fmaf(w, r.x, acc[0]);
    acc[1] = fmaf(w, r.y, acc[1]);
    acc[2] = fmaf(w, r.z, acc[2]);
    acc[3] = fmaf(w, r.w, acc[3]);
}
__device__ __forceinline__ void accum2(float* acc, const float* p, float w) {
    float2 r = *reinterpret_cast<const float2*>(p);
    acc[0] = fmaf(w, r.x, acc[0]);
    acc[1] = fmaf(w, r.y, acc[1]);
}

template <int C>
__global__ __launch_bounds__(256) void prop_kernel(
    const float* __restrict__ in, int in_stride,
    float* __restrict__ out, int out_stride,
    const float* __restrict__ add, int add_stride,
    float alpha, float beta,
    const float* __restrict__ bias, int do_relu, int Nn)
{
    constexpr int V = C / 32;
    int gw = (blockIdx.x * blockDim.x + threadIdx.x) >> 5;
    int lane = threadIdx.x & 31;
    if (gw >= Nn) return;

    int start = g_rowstart[gw];
    int cnt = g_cnt[gw];
    float acc[V];
#pragma unroll
    for (int v = 0; v < V; v++) acc[v] = 0.f;

    const int feat = lane * V;
    int e = 0;
    for (; e + 4 <= cnt; e += 4) {
        int s0 = g_csr_src[start + e + 0];
        int s1 = g_csr_src[start + e + 1];
        int s2 = g_csr_src[start + e + 2];
        int s3 = g_csr_src[start + e + 3];
        float w0 = g_csr_w[start + e + 0];
        float w1 = g_csr_w[start + e + 1];
        float w2 = g_csr_w[start + e + 2];
        float w3 = g_csr_w[start + e + 3];
        const float* p0 = in + (size_t)s0 * in_stride + feat;
        const float* p1 = in + (size_t)s1 * in_stride + feat;
        const float* p2 = in + (size_t)s2 * in_stride + feat;
        const float* p3 = in + (size_t)s3 * in_stride + feat;
        if (V == 4) {
            accum4(acc, p0, w0); accum4(acc, p1, w1);
            accum4(acc, p2, w2); accum4(acc, p3, w3);
        } else {
            accum2(acc, p0, w0); accum2(acc, p1, w1);
            accum2(acc, p2, w2); accum2(acc, p3, w3);
        }
    }
    for (; e < cnt; e++) {
        int s = g_csr_src[start + e];
        float w = g_csr_w[start + e];
        const float* p = in + (size_t)s * in_stride + feat;
        if (V == 4) accum4(acc, p, w);
        else        accum2(acc, p, w);
    }

    float res[V];
#pragma unroll
    for (int v = 0; v < V; v++) res[v] = alpha * acc[v];
    if (add) {
        const float* ap = add + (size_t)gw * add_stride + feat;
        if (V == 4) {
            float4 a = *reinterpret_cast<const float4*>(ap);
            res[0] = fmaf(beta, a.x, res[0]);
            res[1] = fmaf(beta, a.y, res[1]);
            res[2] = fmaf(beta, a.z, res[2]);
            res[3] = fmaf(beta, a.w, res[3]);
        } else {
            float2 a = *reinterpret_cast<const float2*>(ap);
            res[0] = fmaf(beta, a.x, res[0]);
            res[1] = fmaf(beta, a.y, res[1]);
        }
    }
    if (bias) {
#pragma unroll
        for (int v = 0; v < V; v++) res[v] += bias[feat + v];
    }
    if (do_relu) {
#pragma unroll
        for (int v = 0; v < V; v++) res[v] = fmaxf(res[v], 0.f);
    }
    float* op = out + (size_t)gw * out_stride + feat;
    if (V == 4) {
        *reinterpret_cast<float4*>(op) = make_float4(res[0], res[1], res[2], res[3]);
    } else {
        *reinterpret_cast<float2*>(op) = make_float2(res[0], res[1]);
    }
}

// ---------------- launch ----------------------------------------------------
extern "C" void kernel_launch(void* const* d_in, const int* in_sizes, int n_in,
                              void* d_out, int out_size)
{
    const float* x  = (const float*)d_in[0];
    const void*  ei = d_in[1];
    const float* W1 = (const float*)d_in[3];
    const float* b1 = (const float*)d_in[4];
    const float* W2 = (const float*)d_in[5];
    const float* b2 = (const float*)d_in[6];
    const float* W3 = (const float*)d_in[7];
    const float* b3 = (const float*)d_in[8];

    int N = in_sizes[2];      // batch vector has N entries
    int E = in_sizes[1] / 2;

    float *Y, *U, *H2, *H3, *Wc;
    cudaGetSymbolAddress((void**)&Y,  g_Y);
    cudaGetSymbolAddress((void**)&U,  g_U);
    cudaGetSymbolAddress((void**)&H2, g_H2);
    cudaGetSymbolAddress((void**)&H3, g_H3);
    cudaGetSymbolAddress((void**)&Wc, g_Wcat);

    int nblk = (N + 255) / 256;
    int eblk = (E + 255) / 256;
    int nb1024 = (N + 1023) / 1024;
    int pblk = (N + 7) / 8;   // 8 warps / block
    int mgrid = (N + 127) / 128;

    // 1: init (+dtype detect)
    init_kernel<<<nblk, 256>>>((const int*)ei, E, N);
    // 2: weight concat for layer 1
    wcat_kernel<<<(128 * 192 + 255) / 256, 256>>>(W1, Wc);
    // 3: degree counting
    deg_cnt_kernel<<<eblk, 256>>>(ei, E);
    // 4: GEMM1 — positioned here so ncu (-s 5) profiles it
    {
        dim3 g(192 / 64, mgrid);
        gemm_kernel<<<g, 256>>>(x, 128, Wc, 192, Y, 192, N, 192, 128, nullptr, 0);
    }
    // 5-7: dinv + prefix scan of in-degrees
    scan1_kernel<<<nb1024, 1024>>>(N);
    scan2_kernel<<<1, 256>>>(nb1024);
    scan3_kernel<<<nb1024, 1024>>>(N);
    // 8: CSR fill
    fill_kernel<<<eblk, 256>>>(ei, E);

    // ---- layer 1 (output-space propagation):
    // out1 = relu( x(W0-W2) + L(xW1 + 2 L(xW2)) + b1 )
    prop_kernel<64><<<pblk, 256>>>(Y + 64, 192, U, 64, Y, 192, 2.f, 1.f, nullptr, 0, N);
    prop_kernel<64><<<pblk, 256>>>(U, 64, H2, 192, Y + 128, 192, 1.f, 1.f, b1, 1, N);

    // ---- layer 2 ----
    prop_kernel<64><<<pblk, 256>>>(H2, 192, H2 + 64, 192, nullptr, 0, 1.f, 0.f, nullptr, 0, N);
    prop_kernel<64><<<pblk, 256>>>(H2 + 64, 192, H2 + 128, 192, H2, 192, 2.f, -1.f, nullptr, 0, N);
    {
        dim3 g(1, mgrid);
        gemm128_kernel<<<g, 256>>>(H2, 192, W2, 128, H3, 384, N, 192, b2, 1);
    }

    // ---- layer 3 ----
    prop_kernel<128><<<pblk, 256>>>(H3, 384, H3 + 128, 384, nullptr, 0, 1.f, 0.f, nullptr, 0, N);
    prop_kernel<128><<<pblk, 256>>>(H3 + 128, 384, H3 + 256, 384, H3, 384, 2.f, -1.f, nullptr, 0, N);
    {
        dim3 g(2, mgrid);
        gemm128_kernel<<<g, 256>>>(H3, 384, W3, 256, (float*)d_out, 256, N, 384, b3, 0);
    }
}

// round 9
// speedup vs baseline: 1.9211x; 1.9211x over previous
#include <cuda_runtime.h>
#include <cuda_bf16.h>
#include <cstdint>

// ---------------- problem-size constants (fixed by the dataset) -------------
#define MAXN 100000
#define MAXE 1600000

// ---------------- device scratch (allocation-free rule: __device__ globals) -
__device__ __align__(16) float g_Y [MAXN * 256];   // [y1 | y2 | y0 | pad], stride 256
__device__ __align__(16) float g_U [MAXN * 64];    // u = y1 + 2*L y2
__device__ __align__(16) float g_H2[MAXN * 192];   // [h1 | t1 | t2] for layer 2
__device__ __align__(16) float g_H3[MAXN * 384];   // [h2 | t1 | t2] for layer 3
__device__ __align__(16) float g_Wcat[128 * 256];  // [W1_1 | W1_2 | W1_0-W1_2 | 0]

__device__ float g_dinv[MAXN];
__device__ int   g_deg [MAXN];
__device__ int   g_cnt [MAXN];
__device__ int   g_cur [MAXN];
__device__ int   g_rowstart[MAXN];
__device__ int   g_blocksums[256];
__device__ int   g_csr_src[MAXE];
__device__ float g_csr_w [MAXE];
__device__ int   g_is64;          // 1 if edge_index is int64, 0 if int32

// ---------------- packed f32x2 helpers (sm_103a) ----------------------------
__device__ __forceinline__ unsigned long long pack2(float x, float y) {
    unsigned long long r;
    asm("mov.b64 %0, {%1, %2};" : "=l"(r) : "f"(x), "f"(y));
    return r;
}
__device__ __forceinline__ float2 unpack2(unsigned long long v) {
    float2 r;
    asm("mov.b64 {%0, %1}, %2;" : "=f"(r.x), "=f"(r.y) : "l"(v));
    return r;
}
__device__ __forceinline__ void fma2(unsigned long long& d,
                                     unsigned long long a,
                                     unsigned long long b) {
    asm("fma.rn.f32x2 %0, %1, %2, %3;" : "=l"(d) : "l"(a), "l"(b), "l"(d));
}

// ---------------- edge dtype detection + access -----------------------------
__device__ __forceinline__ void load_edge(const void* ei, int e, int E, int is64,
                                          int& s, int& d) {
    if (is64) {
        const long long* p = (const long long*)ei;
        s = (int)p[e];
        d = (int)p[E + e];
    } else {
        const int* p = (const int*)ei;
        s = p[e];
        d = p[E + e];
    }
}

// ---------------- setup kernels ---------------------------------------------
__global__ void init_kernel(const int* __restrict__ ei32, int E, int N) {
    int i = blockIdx.x * blockDim.x + threadIdx.x;
    if (i < N) { g_deg[i] = 0; g_cnt[i] = 0; g_cur[i] = 0; }
    if (i == 0) {
        int is64 = 1;
        int nchk = (E < 64) ? E : 64;
        for (int j = 0; j < nchk; j++) {
            if (ei32[2 * j + 1] != 0) { is64 = 0; break; }
        }
        g_is64 = is64;
    }
}

__global__ void deg_cnt_kernel(const void* __restrict__ ei, int E) {
    int e = blockIdx.x * blockDim.x + threadIdx.x;
    if (e >= E) return;
    int is64 = g_is64;
    int s, d;
    load_edge(ei, e, E, is64, s, d);
    if (s != d) {
        atomicAdd(&g_deg[s], 1);
        atomicAdd(&g_cnt[d], 1);
    }
}

__global__ void scan1_kernel(int N) {
    __shared__ int sm[1024];
    int t = threadIdx.x;
    int i = blockIdx.x * 1024 + t;
    if (i < N) {
        int dg = g_deg[i];
        g_dinv[i] = (dg > 0) ? rsqrtf((float)dg) : 0.0f;
    }
    int v = (i < N) ? g_cnt[i] : 0;
    sm[t] = v;
    __syncthreads();
    for (int off = 1; off < 1024; off <<= 1) {
        int x = (t >= off) ? sm[t - off] : 0;
        __syncthreads();
        sm[t] += x;
        __syncthreads();
    }
    if (i < N) g_rowstart[i] = sm[t] - v;
    if (t == 1023) g_blocksums[blockIdx.x] = sm[1023];
}

__global__ void scan2_kernel(int nb) {
    __shared__ int sm[256];
    int t = threadIdx.x;
    int v = (t < nb) ? g_blocksums[t] : 0;
    sm[t] = v;
    __syncthreads();
    for (int off = 1; off < 256; off <<= 1) {
        int x = (t >= off) ? sm[t - off] : 0;
        __syncthreads();
        sm[t] += x;
        __syncthreads();
    }
    if (t < nb) g_blocksums[t] = sm[t] - v;
}

__global__ void scan3_kernel(int N) {
    int i = blockIdx.x * 1024 + threadIdx.x;
    if (i < N) g_rowstart[i] += g_blocksums[blockIdx.x];
}

__global__ void fill_kernel(const void* __restrict__ ei, int E) {
    int e = blockIdx.x * blockDim.x + threadIdx.x;
    if (e >= E) return;
    int is64 = g_is64;
    int s, d;
    load_edge(ei, e, E, is64, s, d);
    if (s != d) {
        float w = -g_dinv[s] * g_dinv[d];
        int p = g_rowstart[d] + atomicAdd(&g_cur[d], 1);
        g_csr_src[p] = s;
        g_csr_w[p]   = w;
    }
}

// Wcat = [W1[1] | W1[2] | W1[0]-W1[2] | zeros]   (128 x 256)
__global__ void wcat_kernel(const float* __restrict__ W1, float* __restrict__ Wc) {
    int idx = blockIdx.x * blockDim.x + threadIdx.x;
    if (idx >= 128 * 256) return;
    int i = idx / 256, j = idx % 256;
    float v;
    if (j < 64)        v = W1[8192     + i * 64 + j];
    else if (j < 128)  v = W1[2 * 8192 + i * 64 + (j - 64)];
    else if (j < 192)  v = W1[           i * 64 + (j - 128)]
                         - W1[2 * 8192 + i * 64 + (j - 128)];
    else               v = 0.f;
    Wc[idx] = v;
}

// ---------------- GEMM: C[M,N] = A[M,K] @ B[K,N] (+bias)(+relu) -------------
// BM=128, BN=128, BK=32; 256 threads; 8x8 micro-tile.
// Both smem tiles are PLAIN floats (no duplication): B pairs come free from
// LDS.128 (two adjacent N-cols per 64-bit word); A is duplicated into {a,a}
// registers via ALU movs (idle pipe). 64 LDS-bytes per 32 FFMA2 = 2 B/FFMA2.
// Requires K % 32 == 0, N % 128 == 0.
__global__ __launch_bounds__(256) void gemm_kernel(
    const float* __restrict__ A, int lda,
    const float* __restrict__ B, int ldb,
    float* __restrict__ C, int ldc,
    int M, int K,
    const float* __restrict__ bias, int do_relu)
{
    __shared__ __align__(16) float As[32][132];   // transposed: As[k][m]
    __shared__ __align__(16) float Bs[32][132];   // natural:    Bs[k][n]

    int tid = threadIdx.x;
    int tx = tid & 15;        // col group: cols tx*8 .. +7
    int ty = tid >> 4;        // row group: rows ty*8 .. +7
    int m0 = blockIdx.y * 128;
    int n0 = blockIdx.x * 128;

    unsigned long long acc[8][4];   // acc[i][j] = {C[r+i][c+2j], C[r+i][c+2j+1]}
#pragma unroll
    for (int i = 0; i < 8; i++)
#pragma unroll
        for (int j = 0; j < 4; j++) acc[i][j] = 0ull;

    for (int kt = 0; kt < K; kt += 32) {
        // A tile 128x32: float4 along K, store transposed
#pragma unroll
        for (int i = 0; i < 4; i++) {
            int f = tid + i * 256;
            int m = f >> 3;
            int kk = (f & 7) << 2;
            float4 v = make_float4(0.f, 0.f, 0.f, 0.f);
            int row = m0 + m;
            if (row < M)
                v = *reinterpret_cast<const float4*>(A + (size_t)row * lda + kt + kk);
            As[kk + 0][m] = v.x;
            As[kk + 1][m] = v.y;
            As[kk + 2][m] = v.z;
            As[kk + 3][m] = v.w;
        }
        // B tile 32x128: natural layout, straight float4 copy
#pragma unroll
        for (int i = 0; i < 4; i++) {
            int f = tid + i * 256;
            int k = f >> 5;
            int nn = (f & 31) << 2;
            float4 v = *reinterpret_cast<const float4*>(B + (size_t)(kt + k) * ldb + n0 + nn);
            *reinterpret_cast<float4*>(&Bs[k][nn]) = v;
        }
        __syncthreads();
#pragma unroll 8
        for (int k = 0; k < 32; k++) {
            float4 a0 = *reinterpret_cast<const float4*>(&As[k][ty << 3]);
            float4 a1 = *reinterpret_cast<const float4*>(&As[k][(ty << 3) + 4]);
            ulonglong2 b01 = *reinterpret_cast<const ulonglong2*>(&Bs[k][tx << 3]);
            ulonglong2 b23 = *reinterpret_cast<const ulonglong2*>(&Bs[k][(tx << 3) + 4]);
            unsigned long long av[8];
            av[0] = pack2(a0.x, a0.x); av[1] = pack2(a0.y, a0.y);
            av[2] = pack2(a0.z, a0.z); av[3] = pack2(a0.w, a0.w);
            av[4] = pack2(a1.x, a1.x); av[5] = pack2(a1.y, a1.y);
            av[6] = pack2(a1.z, a1.z); av[7] = pack2(a1.w, a1.w);
            unsigned long long bp[4] = {b01.x, b01.y, b23.x, b23.y};
#pragma unroll
            for (int i = 0; i < 8; i++)
#pragma unroll
                for (int j = 0; j < 4; j++)
                    fma2(acc[i][j], av[i], bp[j]);
        }
        __syncthreads();
    }

    float bb[8];
#pragma unroll
    for (int j = 0; j < 8; j++)
        bb[j] = bias ? bias[n0 + (tx << 3) + j] : 0.f;

#pragma unroll
    for (int i = 0; i < 8; i++) {
        int row = m0 + (ty << 3) + i;
        if (row >= M) break;
        float o[8];
#pragma unroll
        for (int j = 0; j < 4; j++) {
            float2 v = unpack2(acc[i][j]);
            o[2 * j]     = v.x + bb[2 * j];
            o[2 * j + 1] = v.y + bb[2 * j + 1];
        }
        if (do_relu) {
#pragma unroll
            for (int j = 0; j < 8; j++) o[j] = fmaxf(o[j], 0.f);
        }
        float* p = C + (size_t)row * ldc + n0 + (tx << 3);
        *reinterpret_cast<float4*>(p)     = make_float4(o[0], o[1], o[2], o[3]);
        *reinterpret_cast<float4*>(p + 4) = make_float4(o[4], o[5], o[6], o[7]);
    }
}

// ---------------- propagation: out = alpha*(L @ in) + beta*add + bias, relu -
__device__ __forceinline__ void accum4(float* acc, const float* p, float w) {
    float4 r = *reinterpret_cast<const float4*>(p);
    acc[0] = fmaf(w, r.x, acc[0]);
    acc[1] = fmaf(w, r.y, acc[1]);
    acc[2] = fmaf(w, r.z, acc[2]);
    acc[3] = fmaf(w, r.w, acc[3]);
}
__device__ __forceinline__ void accum2(float* acc, const float* p, float w) {
    float2 r = *reinterpret_cast<const float2*>(p);
    acc[0] = fmaf(w, r.x, acc[0]);
    acc[1] = fmaf(w, r.y, acc[1]);
}

template <int C>
__global__ __launch_bounds__(256) void prop_kernel(
    const float* __restrict__ in, int in_stride,
    float* __restrict__ out, int out_stride,
    const float* __restrict__ add, int add_stride,
    float alpha, float beta,
    const float* __restrict__ bias, int do_relu, int Nn)
{
    constexpr int V = C / 32;
    int gw = (blockIdx.x * blockDim.x + threadIdx.x) >> 5;
    int lane = threadIdx.x & 31;
    if (gw >= Nn) return;

    int start = g_rowstart[gw];
    int cnt = g_cnt[gw];
    float acc[V];
#pragma unroll
    for (int v = 0; v < V; v++) acc[v] = 0.f;

    const int feat = lane * V;
    int e = 0;
    for (; e + 4 <= cnt; e += 4) {
        int s0 = g_csr_src[start + e + 0];
        int s1 = g_csr_src[start + e + 1];
        int s2 = g_csr_src[start + e + 2];
        int s3 = g_csr_src[start + e + 3];
        float w0 = g_csr_w[start + e + 0];
        float w1 = g_csr_w[start + e + 1];
        float w2 = g_csr_w[start + e + 2];
        float w3 = g_csr_w[start + e + 3];
        const float* p0 = in + (size_t)s0 * in_stride + feat;
        const float* p1 = in + (size_t)s1 * in_stride + feat;
        const float* p2 = in + (size_t)s2 * in_stride + feat;
        const float* p3 = in + (size_t)s3 * in_stride + feat;
        if (V == 4) {
            accum4(acc, p0, w0); accum4(acc, p1, w1);
            accum4(acc, p2, w2); accum4(acc, p3, w3);
        } else {
            accum2(acc, p0, w0); accum2(acc, p1, w1);
            accum2(acc, p2, w2); accum2(acc, p3, w3);
        }
    }
    for (; e < cnt; e++) {
        int s = g_csr_src[start + e];
        float w = g_csr_w[start + e];
        const float* p = in + (size_t)s * in_stride + feat;
        if (V == 4) accum4(acc, p, w);
        else        accum2(acc, p, w);
    }

    float res[V];
#pragma unroll
    for (int v = 0; v < V; v++) res[v] = alpha * acc[v];
    if (add) {
        const float* ap = add + (size_t)gw * add_stride + feat;
        if (V == 4) {
            float4 a = *reinterpret_cast<const float4*>(ap);
            res[0] = fmaf(beta, a.x, res[0]);
            res[1] = fmaf(beta, a.y, res[1]);
            res[2] = fmaf(beta, a.z, res[2]);
            res[3] = fmaf(beta, a.w, res[3]);
        } else {
            float2 a = *reinterpret_cast<const float2*>(ap);
            res[0] = fmaf(beta, a.x, res[0]);
            res[1] = fmaf(beta, a.y, res[1]);
        }
    }
    if (bias) {
#pragma unroll
        for (int v = 0; v < V; v++) res[v] += bias[feat + v];
    }
    if (do_relu) {
#pragma unroll
        for (int v = 0; v < V; v++) res[v] = fmaxf(res[v], 0.f);
    }
    float* op = out + (size_t)gw * out_stride + feat;
    if (V == 4) {
        *reinterpret_cast<float4*>(op) = make_float4(res[0], res[1], res[2], res[3]);
    } else {
        *reinterpret_cast<float2*>(op) = make_float2(res[0], res[1]);
    }
}

// ---------------- launch ----------------------------------------------------
extern "C" void kernel_launch(void* const* d_in, const int* in_sizes, int n_in,
                              void* d_out, int out_size)
{
    const float* x  = (const float*)d_in[0];
    const void*  ei = d_in[1];
    const float* W1 = (const float*)d_in[3];
    const float* b1 = (const float*)d_in[4];
    const float* W2 = (const float*)d_in[5];
    const float* b2 = (const float*)d_in[6];
    const float* W3 = (const float*)d_in[7];
    const float* b3 = (const float*)d_in[8];

    int N = in_sizes[2];      // batch vector has N entries
    int E = in_sizes[1] / 2;

    float *Y, *U, *H2, *H3, *Wc;
    cudaGetSymbolAddress((void**)&Y,  g_Y);
    cudaGetSymbolAddress((void**)&U,  g_U);
    cudaGetSymbolAddress((void**)&H2, g_H2);
    cudaGetSymbolAddress((void**)&H3, g_H3);
    cudaGetSymbolAddress((void**)&Wc, g_Wcat);

    int nblk = (N + 255) / 256;
    int eblk = (E + 255) / 256;
    int nb1024 = (N + 1023) / 1024;
    int pblk = (N + 7) / 8;   // 8 warps / block
    int mgrid = (N + 127) / 128;

    // 1: init (+dtype detect)
    init_kernel<<<nblk, 256>>>((const int*)ei, E, N);
    // 2: weight concat for layer 1 (padded to 256 cols)
    wcat_kernel<<<(128 * 256 + 255) / 256, 256>>>(W1, Wc);
    // 3: degree counting
    deg_cnt_kernel<<<eblk, 256>>>(ei, E);
    // 4: GEMM1 — positioned here so ncu (-s 5) profiles it
    //    Y[:,0:192] = x @ [W1_1 | W1_2 | W1_0-W1_2], cols 192..255 pad
    {
        dim3 g(2, mgrid);
        gemm_kernel<<<g, 256>>>(x, 128, Wc, 256, Y, 256, N, 128, nullptr, 0);
    }
    // 5-7: dinv + prefix scan of in-degrees
    scan1_kernel<<<nb1024, 1024>>>(N);
    scan2_kernel<<<1, 256>>>(nb1024);
    scan3_kernel<<<nb1024, 1024>>>(N);
    // 8: CSR fill
    fill_kernel<<<eblk, 256>>>(ei, E);

    // ---- layer 1 (output-space propagation):
    // out1 = relu( x(W0-W2) + L(xW1 + 2 L(xW2)) + b1 )
    // Y layout (stride 256): [y1 | y2 | y0 | pad]
    prop_kernel<64><<<pblk, 256>>>(Y + 64, 256, U, 64, Y, 256, 2.f, 1.f, nullptr, 0, N);
    prop_kernel<64><<<pblk, 256>>>(U, 64, H2, 192, Y + 128, 256, 1.f, 1.f, b1, 1, N);

    // ---- layer 2 ----
    prop_kernel<64><<<pblk, 256>>>(H2, 192, H2 + 64, 192, nullptr, 0, 1.f, 0.f, nullptr, 0, N);
    prop_kernel<64><<<pblk, 256>>>(H2 + 64, 192, H2 + 128, 192, H2, 192, 2.f, -1.f, nullptr, 0, N);
    {
        dim3 g(1, mgrid);
        gemm_kernel<<<g, 256>>>(H2, 192, W2, 128, H3, 384, N, 192, b2, 1);
    }

    // ---- layer 3 ----
    prop_kernel<128><<<pblk, 256>>>(H3, 384, H3 + 128, 384, nullptr, 0, 1.f, 0.f, nullptr, 0, N);
    prop_kernel<128><<<pblk, 256>>>(H3 + 128, 384, H3 + 256, 384, H3, 384, 2.f, -1.f, nullptr, 0, N);
    {
        dim3 g(2, mgrid);
        gemm_kernel<<<g, 256>>>(H3, 384, W3, 256, (float*)d_out, 256, N, 384, b3, 0);
    }
}

// round 10
// speedup vs baseline: 2.0759x; 1.0806x over previous
#include <cuda_runtime.h>
#include <cuda_bf16.h>
#include <cstdint>

// ---------------- problem-size constants (fixed by the dataset) -------------
#define MAXN 100000
#define MAXE 1600000

// ---------------- device scratch (allocation-free rule: __device__ globals) -
__device__ __align__(16) float g_Y [MAXN * 256];   // [y1 | y2 | y0 | pad], stride 256
__device__ __align__(16) float g_U [MAXN * 64];    // u = y1 + 2*L y2
__device__ __align__(16) float g_H2[MAXN * 192];   // [h1 | t1 | t2] for layer 2
__device__ __align__(16) float g_H3[MAXN * 384];   // [h2 | t1 | t2] for layer 3
__device__ __align__(16) float g_Wcat[128 * 256];  // [W1_1 | W1_2 | W1_0-W1_2 | 0]

__device__ float g_dinv[MAXN];
__device__ int   g_deg [MAXN];
__device__ int   g_cnt [MAXN];
__device__ int   g_cur [MAXN];
__device__ int   g_rowstart[MAXN];
__device__ int   g_blocksums[256];
__device__ int   g_csr_src[MAXE];
__device__ float g_csr_w [MAXE];
__device__ int   g_is64;          // 1 if edge_index is int64, 0 if int32

// ---------------- packed f32x2 helpers (sm_103a) ----------------------------
__device__ __forceinline__ unsigned long long pack2(float x, float y) {
    unsigned long long r;
    asm("mov.b64 %0, {%1, %2};" : "=l"(r) : "f"(x), "f"(y));
    return r;
}
__device__ __forceinline__ float2 unpack2(unsigned long long v) {
    float2 r;
    asm("mov.b64 {%0, %1}, %2;" : "=f"(r.x), "=f"(r.y) : "l"(v));
    return r;
}
__device__ __forceinline__ void fma2(unsigned long long& d,
                                     unsigned long long a,
                                     unsigned long long b) {
    asm("fma.rn.f32x2 %0, %1, %2, %3;" : "=l"(d) : "l"(a), "l"(b), "l"(d));
}

// ---------------- edge dtype detection + access -----------------------------
__device__ __forceinline__ void load_edge(const void* ei, int e, int E, int is64,
                                          int& s, int& d) {
    if (is64) {
        const long long* p = (const long long*)ei;
        s = (int)p[e];
        d = (int)p[E + e];
    } else {
        const int* p = (const int*)ei;
        s = p[e];
        d = p[E + e];
    }
}

// ---------------- setup kernels ---------------------------------------------
__global__ void init_kernel(const int* __restrict__ ei32, int E, int N) {
    int i = blockIdx.x * blockDim.x + threadIdx.x;
    if (i < N) { g_deg[i] = 0; g_cnt[i] = 0; g_cur[i] = 0; }
    if (i == 0) {
        int is64 = 1;
        int nchk = (E < 64) ? E : 64;
        for (int j = 0; j < nchk; j++) {
            if (ei32[2 * j + 1] != 0) { is64 = 0; break; }
        }
        g_is64 = is64;
    }
}

__global__ void deg_cnt_kernel(const void* __restrict__ ei, int E) {
    int e = blockIdx.x * blockDim.x + threadIdx.x;
    if (e >= E) return;
    int is64 = g_is64;
    int s, d;
    load_edge(ei, e, E, is64, s, d);
    if (s != d) {
        atomicAdd(&g_deg[s], 1);
        atomicAdd(&g_cnt[d], 1);
    }
}

__global__ void scan1_kernel(int N) {
    __shared__ int sm[1024];
    int t = threadIdx.x;
    int i = blockIdx.x * 1024 + t;
    if (i < N) {
        int dg = g_deg[i];
        g_dinv[i] = (dg > 0) ? rsqrtf((float)dg) : 0.0f;
    }
    int v = (i < N) ? g_cnt[i] : 0;
    sm[t] = v;
    __syncthreads();
    for (int off = 1; off < 1024; off <<= 1) {
        int x = (t >= off) ? sm[t - off] : 0;
        __syncthreads();
        sm[t] += x;
        __syncthreads();
    }
    if (i < N) g_rowstart[i] = sm[t] - v;
    if (t == 1023) g_blocksums[blockIdx.x] = sm[1023];
}

__global__ void scan2_kernel(int nb) {
    __shared__ int sm[256];
    int t = threadIdx.x;
    int v = (t < nb) ? g_blocksums[t] : 0;
    sm[t] = v;
    __syncthreads();
    for (int off = 1; off < 256; off <<= 1) {
        int x = (t >= off) ? sm[t - off] : 0;
        __syncthreads();
        sm[t] += x;
        __syncthreads();
    }
    if (t < nb) g_blocksums[t] = sm[t] - v;
}

__global__ void scan3_kernel(int N) {
    int i = blockIdx.x * 1024 + threadIdx.x;
    if (i < N) g_rowstart[i] += g_blocksums[blockIdx.x];
}

__global__ void fill_kernel(const void* __restrict__ ei, int E) {
    int e = blockIdx.x * blockDim.x + threadIdx.x;
    if (e >= E) return;
    int is64 = g_is64;
    int s, d;
    load_edge(ei, e, E, is64, s, d);
    if (s != d) {
        float w = -g_dinv[s] * g_dinv[d];
        int p = g_rowstart[d] + atomicAdd(&g_cur[d], 1);
        g_csr_src[p] = s;
        g_csr_w[p]   = w;
    }
}

// Wcat = [W1[1] | W1[2] | W1[0]-W1[2] | zeros]   (128 x 256)
__global__ void wcat_kernel(const float* __restrict__ W1, float* __restrict__ Wc) {
    int idx = blockIdx.x * blockDim.x + threadIdx.x;
    if (idx >= 128 * 256) return;
    int i = idx / 256, j = idx % 256;
    float v;
    if (j < 64)        v = W1[8192     + i * 64 + j];
    else if (j < 128)  v = W1[2 * 8192 + i * 64 + (j - 64)];
    else if (j < 192)  v = W1[           i * 64 + (j - 128)]
                         - W1[2 * 8192 + i * 64 + (j - 128)];
    else               v = 0.f;
    Wc[idx] = v;
}

// Bs swizzle: insert a 16B gap every 128B so that strided 32B reads hit
// distinct banks in both LDS phases. idx(c) = c + 4*(c>>5); row = 144 floats.
__device__ __forceinline__ int bswz(int c) { return c + ((c >> 5) << 2); }

// ---------------- GEMM: C[M,N] = A[M,K] @ B[K,N] (+bias)(+relu) -------------
// BM=128, BN=128, BK=32; 256 threads; 8x8 micro-tile.
// Warp shape 8tx x 4ty: each B LDS.128 touches 128B (1 wavefront, swizzled
// conflict-free), each A LDS.128 touches 64B. ~4 crossbar cyc per k per warp
// vs 32 FFMA2 -> FMA-issue-bound.
// Requires K % 32 == 0, N % 128 == 0.
__global__ __launch_bounds__(256) void gemm_kernel(
    const float* __restrict__ A, int lda,
    const float* __restrict__ B, int ldb,
    float* __restrict__ C, int ldc,
    int M, int K,
    const float* __restrict__ bias, int do_relu)
{
    __shared__ __align__(16) float As[32][132];   // transposed: As[k][m]
    __shared__ __align__(16) float Bs[32][144];   // natural, swizzled: Bs[k][bswz(n)]

    int tid = threadIdx.x;
    int lane = tid & 31;
    // warp shape 8 tx-groups x 4 ty-groups
    int tx = (((tid >> 5) & 1) << 3) | (lane & 7);   // 0..15, col group (cols tx*8..+7)
    int ty = ((tid >> 6) << 2) | (lane >> 3);        // 0..15, row group (rows ty*8..+7)
    int m0 = blockIdx.y * 128;
    int n0 = blockIdx.x * 128;

    const int bi1 = bswz(tx << 3);         // swizzled float idx of cols tx*8..+3
    const int bi2 = bswz((tx << 3) + 4);   // cols tx*8+4..+7

    unsigned long long acc[8][4];   // acc[i][j] = {C[r+i][c+2j], C[r+i][c+2j+1]}
#pragma unroll
    for (int i = 0; i < 8; i++)
#pragma unroll
        for (int j = 0; j < 4; j++) acc[i][j] = 0ull;

    for (int kt = 0; kt < K; kt += 32) {
        // A tile 128x32: float4 along K, store transposed
#pragma unroll
        for (int i = 0; i < 4; i++) {
            int f = tid + i * 256;
            int m = f >> 3;
            int kk = (f & 7) << 2;
            float4 v = make_float4(0.f, 0.f, 0.f, 0.f);
            int row = m0 + m;
            if (row < M)
                v = *reinterpret_cast<const float4*>(A + (size_t)row * lda + kt + kk);
            As[kk + 0][m] = v.x;
            As[kk + 1][m] = v.y;
            As[kk + 2][m] = v.z;
            As[kk + 3][m] = v.w;
        }
        // B tile 32x128: natural layout, swizzled float4 copy
#pragma unroll
        for (int i = 0; i < 4; i++) {
            int f = tid + i * 256;
            int k = f >> 5;
            int nn = (f & 31) << 2;
            float4 v = *reinterpret_cast<const float4*>(B + (size_t)(kt + k) * ldb + n0 + nn);
            *reinterpret_cast<float4*>(&Bs[k][bswz(nn)]) = v;
        }
        __syncthreads();
#pragma unroll 8
        for (int k = 0; k < 32; k++) {
            float4 a0 = *reinterpret_cast<const float4*>(&As[k][ty << 3]);
            float4 a1 = *reinterpret_cast<const float4*>(&As[k][(ty << 3) + 4]);
            ulonglong2 b01 = *reinterpret_cast<const ulonglong2*>(&Bs[k][bi1]);
            ulonglong2 b23 = *reinterpret_cast<const ulonglong2*>(&Bs[k][bi2]);
            unsigned long long av[8];
            av[0] = pack2(a0.x, a0.x); av[1] = pack2(a0.y, a0.y);
            av[2] = pack2(a0.z, a0.z); av[3] = pack2(a0.w, a0.w);
            av[4] = pack2(a1.x, a1.x); av[5] = pack2(a1.y, a1.y);
            av[6] = pack2(a1.z, a1.z); av[7] = pack2(a1.w, a1.w);
            unsigned long long bp[4] = {b01.x, b01.y, b23.x, b23.y};
#pragma unroll
            for (int i = 0; i < 8; i++)
#pragma unroll
                for (int j = 0; j < 4; j++)
                    fma2(acc[i][j], av[i], bp[j]);
        }
        __syncthreads();
    }

    float bb[8];
#pragma unroll
    for (int j = 0; j < 8; j++)
        bb[j] = bias ? bias[n0 + (tx << 3) + j] : 0.f;

#pragma unroll
    for (int i = 0; i < 8; i++) {
        int row = m0 + (ty << 3) + i;
        if (row >= M) break;
        float o[8];
#pragma unroll
        for (int j = 0; j < 4; j++) {
            float2 v = unpack2(acc[i][j]);
            o[2 * j]     = v.x + bb[2 * j];
            o[2 * j + 1] = v.y + bb[2 * j + 1];
        }
        if (do_relu) {
#pragma unroll
            for (int j = 0; j < 8; j++) o[j] = fmaxf(o[j], 0.f);
        }
        float* p = C + (size_t)row * ldc + n0 + (tx << 3);
        *reinterpret_cast<float4*>(p)     = make_float4(o[0], o[1], o[2], o[3]);
        *reinterpret_cast<float4*>(p + 4) = make_float4(o[4], o[5], o[6], o[7]);
    }
}

// ---------------- propagation: out = alpha*(L @ in) + beta*add + bias, relu -
__device__ __forceinline__ void accum4(float* acc, const float* p, float w) {
    float4 r = *reinterpret_cast<const float4*>(p);
    acc[0] = fmaf(w, r.x, acc[0]);
    acc[1] = fmaf(w, r.y, acc[1]);
    acc[2] = fmaf(w, r.z, acc[2]);
    acc[3] = fmaf(w, r.w, acc[3]);
}
__device__ __forceinline__ void accum2(float* acc, const float* p, float w) {
    float2 r = *reinterpret_cast<const float2*>(p);
    acc[0] = fmaf(w, r.x, acc[0]);
    acc[1] = fmaf(w, r.y, acc[1]);
}

template <int C>
__global__ __launch_bounds__(256) void prop_kernel(
    const float* __restrict__ in, int in_stride,
    float* __restrict__ out, int out_stride,
    const float* __restrict__ add, int add_stride,
    float alpha, float beta,
    const float* __restrict__ bias, int do_relu, int Nn)
{
    constexpr int V = C / 32;
    int gw = (blockIdx.x * blockDim.x + threadIdx.x) >> 5;
    int lane = threadIdx.x & 31;
    if (gw >= Nn) return;

    int start = g_rowstart[gw];
    int cnt = g_cnt[gw];
    float acc[V];
#pragma unroll
    for (int v = 0; v < V; v++) acc[v] = 0.f;

    const int feat = lane * V;
    int e = 0;
    for (; e + 4 <= cnt; e += 4) {
        int s0 = g_csr_src[start + e + 0];
        int s1 = g_csr_src[start + e + 1];
        int s2 = g_csr_src[start + e + 2];
        int s3 = g_csr_src[start + e + 3];
        float w0 = g_csr_w[start + e + 0];
        float w1 = g_csr_w[start + e + 1];
        float w2 = g_csr_w[start + e + 2];
        float w3 = g_csr_w[start + e + 3];
        const float* p0 = in + (size_t)s0 * in_stride + feat;
        const float* p1 = in + (size_t)s1 * in_stride + feat;
        const float* p2 = in + (size_t)s2 * in_stride + feat;
        const float* p3 = in + (size_t)s3 * in_stride + feat;
        if (V == 4) {
            accum4(acc, p0, w0); accum4(acc, p1, w1);
            accum4(acc, p2, w2); accum4(acc, p3, w3);
        } else {
            accum2(acc, p0, w0); accum2(acc, p1, w1);
            accum2(acc, p2, w2); accum2(acc, p3, w3);
        }
    }
    for (; e < cnt; e++) {
        int s = g_csr_src[start + e];
        float w = g_csr_w[start + e];
        const float* p = in + (size_t)s * in_stride + feat;
        if (V == 4) accum4(acc, p, w);
        else        accum2(acc, p, w);
    }

    float res[V];
#pragma unroll
    for (int v = 0; v < V; v++) res[v] = alpha * acc[v];
    if (add) {
        const float* ap = add + (size_t)gw * add_stride + feat;
        if (V == 4) {
            float4 a = *reinterpret_cast<const float4*>(ap);
            res[0] = fmaf(beta, a.x, res[0]);
            res[1] = fmaf(beta, a.y, res[1]);
            res[2] = fmaf(beta, a.z, res[2]);
            res[3] = fmaf(beta, a.w, res[3]);
        } else {
            float2 a = *reinterpret_cast<const float2*>(ap);
            res[0] = fmaf(beta, a.x, res[0]);
            res[1] = fmaf(beta, a.y, res[1]);
        }
    }
    if (bias) {
#pragma unroll
        for (int v = 0; v < V; v++) res[v] += bias[feat + v];
    }
    if (do_relu) {
#pragma unroll
        for (int v = 0; v < V; v++) res[v] = fmaxf(res[v], 0.f);
    }
    float* op = out + (size_t)gw * out_stride + feat;
    if (V == 4) {
        *reinterpret_cast<float4*>(op) = make_float4(res[0], res[1], res[2], res[3]);
    } else {
        *reinterpret_cast<float2*>(op) = make_float2(res[0], res[1]);
    }
}

// ---------------- launch ----------------------------------------------------
extern "C" void kernel_launch(void* const* d_in, const int* in_sizes, int n_in,
                              void* d_out, int out_size)
{
    const float* x  = (const float*)d_in[0];
    const void*  ei = d_in[1];
    const float* W1 = (const float*)d_in[3];
    const float* b1 = (const float*)d_in[4];
    const float* W2 = (const float*)d_in[5];
    const float* b2 = (const float*)d_in[6];
    const float* W3 = (const float*)d_in[7];
    const float* b3 = (const float*)d_in[8];

    int N = in_sizes[2];      // batch vector has N entries
    int E = in_sizes[1] / 2;

    float *Y, *U, *H2, *H3, *Wc;
    cudaGetSymbolAddress((void**)&Y,  g_Y);
    cudaGetSymbolAddress((void**)&U,  g_U);
    cudaGetSymbolAddress((void**)&H2, g_H2);
    cudaGetSymbolAddress((void**)&H3, g_H3);
    cudaGetSymbolAddress((void**)&Wc, g_Wcat);

    int nblk = (N + 255) / 256;
    int eblk = (E + 255) / 256;
    int nb1024 = (N + 1023) / 1024;
    int pblk = (N + 7) / 8;   // 8 warps / block
    int mgrid = (N + 127) / 128;

    // 1: init (+dtype detect)
    init_kernel<<<nblk, 256>>>((const int*)ei, E, N);
    // 2: weight concat for layer 1 (padded to 256 cols)
    wcat_kernel<<<(128 * 256 + 255) / 256, 256>>>(W1, Wc);
    // 3: degree counting
    deg_cnt_kernel<<<eblk, 256>>>(ei, E);
    // 4: GEMM1 — positioned here so ncu (-s 5) profiles it
    {
        dim3 g(2, mgrid);
        gemm_kernel<<<g, 256>>>(x, 128, Wc, 256, Y, 256, N, 128, nullptr, 0);
    }
    // 5-7: dinv + prefix scan of in-degrees
    scan1_kernel<<<nb1024, 1024>>>(N);
    scan2_kernel<<<1, 256>>>(nb1024);
    scan3_kernel<<<nb1024, 1024>>>(N);
    // 8: CSR fill
    fill_kernel<<<eblk, 256>>>(ei, E);

    // ---- layer 1 (output-space propagation):
    // out1 = relu( x(W0-W2) + L(xW1 + 2 L(xW2)) + b1 )
    // Y layout (stride 256): [y1 | y2 | y0 | pad]
    prop_kernel<64><<<pblk, 256>>>(Y + 64, 256, U, 64, Y, 256, 2.f, 1.f, nullptr, 0, N);
    prop_kernel<64><<<pblk, 256>>>(U, 64, H2, 192, Y + 128, 256, 1.f, 1.f, b1, 1, N);

    // ---- layer 2 ----
    prop_kernel<64><<<pblk, 256>>>(H2, 192, H2 + 64, 192, nullptr, 0, 1.f, 0.f, nullptr, 0, N);
    prop_kernel<64><<<pblk, 256>>>(H2 + 64, 192, H2 + 128, 192, H2, 192, 2.f, -1.f, nullptr, 0, N);
    {
        dim3 g(1, mgrid);
        gemm_kernel<<<g, 256>>>(H2, 192, W2, 128, H3, 384, N, 192, b2, 1);
    }

    // ---- layer 3 ----
    prop_kernel<128><<<pblk, 256>>>(H3, 384, H3 + 128, 384, nullptr, 0, 1.f, 0.f, nullptr, 0, N);
    prop_kernel<128><<<pblk, 256>>>(H3 + 128, 384, H3 + 256, 384, H3, 384, 2.f, -1.f, nullptr, 0, N);
    {
        dim3 g(2, mgrid);
        gemm_kernel<<<g, 256>>>(H3, 384, W3, 256, (float*)d_out, 256, N, 384, b3, 0);
    }
}

// round 12
// speedup vs baseline: 2.8766x; 1.3857x over previous
#include <cuda_runtime.h>
#include <cuda_bf16.h>
#include <cstdint>

// ---------------- problem-size constants (fixed by the dataset) -------------
#define MAXN 100000
#define MAXE 1600000

// ---------------- device scratch (allocation-free rule: __device__ globals) -
__device__ __align__(16) float g_Y [MAXN * 256];   // [y1 | y2 | y0 | pad], stride 256
__device__ __align__(16) float g_U [MAXN * 64];    // u = y1 + 2*L y2
__device__ __align__(16) float g_H2[MAXN * 192];   // [h1 | t1 | t2] for layer 2
__device__ __align__(16) float g_H3[MAXN * 384];   // [h2 | t1 | t2] for layer 3
__device__ __align__(16) float g_Wcat[128 * 256];  // [W1_1 | W1_2 | W1_0-W1_2 | 0]

// Pre-split bf16 weights, layout Wt[n*K + k] per GEMM (hi and lo parts).
// GEMM1: base 0, 256x128 = 32768; GEMM2: base 32768, 128x192 = 24576;
// GEMM3: base 57344, 256x384 = 98304. Total 155648.
#define WT_TOTAL 155648
__device__ __align__(16) __nv_bfloat16 g_Wth[WT_TOTAL];
__device__ __align__(16) __nv_bfloat16 g_Wtl[WT_TOTAL];

__device__ float g_dinv[MAXN];
__device__ int   g_deg [MAXN];
__device__ int   g_cnt [MAXN];
__device__ int   g_cur [MAXN];
__device__ int   g_rowstart[MAXN];
__device__ int   g_blocksums[256];
__device__ int   g_csr_src[MAXE];
__device__ float g_csr_w [MAXE];
__device__ int   g_is64;          // 1 if edge_index is int64, 0 if int32

// ---------------- PTX helpers (baseline sm_80+ features only) ----------------
__device__ __forceinline__ uint32_t smem_u32(const void* p) {
    uint32_t a;
    asm("{ .reg .u64 t; cvta.to.shared.u64 t, %1; cvt.u32.u64 %0, t; }"
        : "=r"(a) : "l"(p));
    return a;
}
__device__ __forceinline__ void ldsm_x4(uint32_t* r, uint32_t addr) {
    asm volatile("ldmatrix.sync.aligned.m8n8.x4.shared.b16 {%0,%1,%2,%3}, [%4];"
        : "=r"(r[0]), "=r"(r[1]), "=r"(r[2]), "=r"(r[3]) : "r"(addr));
}
__device__ __forceinline__ void mma_bf16(float* c, const uint32_t* a,
                                         uint32_t b0, uint32_t b1) {
    asm volatile(
        "mma.sync.aligned.m16n8k16.row.col.f32.bf16.bf16.f32 "
        "{%0,%1,%2,%3}, {%4,%5,%6,%7}, {%8,%9}, {%0,%1,%2,%3};"
        : "+f"(c[0]), "+f"(c[1]), "+f"(c[2]), "+f"(c[3])
        : "r"(a[0]), "r"(a[1]), "r"(a[2]), "r"(a[3]), "r"(b0), "r"(b1));
}
__device__ __forceinline__ uint32_t bf2u(__nv_bfloat16 a, __nv_bfloat16 b) {
    __nv_bfloat162 p = __halves2bfloat162(a, b);
    return *reinterpret_cast<uint32_t*>(&p);
}

// ---------------- edge dtype detection + access -----------------------------
__device__ __forceinline__ void load_edge(const void* ei, int e, int E, int is64,
                                          int& s, int& d) {
    if (is64) {
        const long long* p = (const long long*)ei;
        s = (int)p[e];
        d = (int)p[E + e];
    } else {
        const int* p = (const int*)ei;
        s = p[e];
        d = p[E + e];
    }
}

// ---------------- setup kernels ---------------------------------------------
__global__ void init_kernel(const int* __restrict__ ei32, int E, int N) {
    int i = blockIdx.x * blockDim.x + threadIdx.x;
    if (i < N) { g_deg[i] = 0; g_cnt[i] = 0; g_cur[i] = 0; }
    if (i == 0) {
        int is64 = 1;
        int nchk = (E < 64) ? E : 64;
        for (int j = 0; j < nchk; j++) {
            if (ei32[2 * j + 1] != 0) { is64 = 0; break; }
        }
        g_is64 = is64;
    }
}

__global__ void deg_cnt_kernel(const void* __restrict__ ei, int E) {
    int e = blockIdx.x * blockDim.x + threadIdx.x;
    if (e >= E) return;
    int is64 = g_is64;
    int s, d;
    load_edge(ei, e, E, is64, s, d);
    if (s != d) {
        atomicAdd(&g_deg[s], 1);
        atomicAdd(&g_cnt[d], 1);
    }
}

__global__ void scan1_kernel(int N) {
    __shared__ int sm[1024];
    int t = threadIdx.x;
    int i = blockIdx.x * 1024 + t;
    if (i < N) {
        int dg = g_deg[i];
        g_dinv[i] = (dg > 0) ? rsqrtf((float)dg) : 0.0f;
    }
    int v = (i < N) ? g_cnt[i] : 0;
    sm[t] = v;
    __syncthreads();
    for (int off = 1; off < 1024; off <<= 1) {
        int x = (t >= off) ? sm[t - off] : 0;
        __syncthreads();
        sm[t] += x;
        __syncthreads();
    }
    if (i < N) g_rowstart[i] = sm[t] - v;
    if (t == 1023) g_blocksums[blockIdx.x] = sm[1023];
}

__global__ void scan2_kernel(int nb) {
    __shared__ int sm[256];
    int t = threadIdx.x;
    int v = (t < nb) ? g_blocksums[t] : 0;
    sm[t] = v;
    __syncthreads();
    for (int off = 1; off < 256; off <<= 1) {
        int x = (t >= off) ? sm[t - off] : 0;
        __syncthreads();
        sm[t] += x;
        __syncthreads();
    }
    if (t < nb) g_blocksums[t] = sm[t] - v;
}

__global__ void scan3_kernel(int N) {
    int i = blockIdx.x * 1024 + threadIdx.x;
    if (i < N) g_rowstart[i] += g_blocksums[blockIdx.x];
}

__global__ void fill_kernel(const void* __restrict__ ei, int E) {
    int e = blockIdx.x * blockDim.x + threadIdx.x;
    if (e >= E) return;
    int is64 = g_is64;
    int s, d;
    load_edge(ei, e, E, is64, s, d);
    if (s != d) {
        float w = -g_dinv[s] * g_dinv[d];
        int p = g_rowstart[d] + atomicAdd(&g_cur[d], 1);
        g_csr_src[p] = s;
        g_csr_w[p]   = w;
    }
}

// Wcat = [W1[1] | W1[2] | W1[0]-W1[2] | zeros]   (128 x 256)
__global__ void wcat_kernel(const float* __restrict__ W1, float* __restrict__ Wc) {
    int idx = blockIdx.x * blockDim.x + threadIdx.x;
    if (idx >= 128 * 256) return;
    int i = idx / 256, j = idx % 256;
    float v;
    if (j < 64)        v = W1[8192     + i * 64 + j];
    else if (j < 128)  v = W1[2 * 8192 + i * 64 + (j - 64)];
    else if (j < 192)  v = W1[           i * 64 + (j - 128)]
                         - W1[2 * 8192 + i * 64 + (j - 128)];
    else               v = 0.f;
    Wc[idx] = v;
}

// Weight prep: W[K,N] fp32 row-major (ld=ldw) -> Wt[n*K+k] bf16 hi/lo.
__global__ void wprep_kernel(const float* __restrict__ W, int ldw,
                             int K, int Ncols, int base) {
    int idx = blockIdx.x * blockDim.x + threadIdx.x;
    if (idx >= K * Ncols) return;
    int n = idx / K, k = idx % K;
    float v = W[(size_t)k * ldw + n];
    __nv_bfloat16 hi = __float2bfloat16(v);
    __nv_bfloat16 lo = __float2bfloat16(v - __bfloat162float(hi));
    g_Wth[base + idx] = hi;
    g_Wtl[base + idx] = lo;
}

// ---------------- mma.sync bf16 GEMM: C = A @ W (+bias)(+relu) ---------------
// bf16x3 split: D += Ah*Bh + Ah*Bl + Al*Bh (fp32 accum in registers).
// CTA tile 128x128, 8 warps (4m x 2n), warp tile 32x64.
// smem rows padded to 80B (20 words) -> LDSM phases bank-conflict-free.
// Requires K % 32 == 0, N % 128 == 0.
#define SMA 80
__global__ __launch_bounds__(256) void mma_gemm(
    const float* __restrict__ A, int lda, int K,
    const __nv_bfloat16* __restrict__ Wh, const __nv_bfloat16* __restrict__ Wl,
    int wbase,
    float* __restrict__ C, int ldc, int M,
    const float* __restrict__ bias, int do_relu)
{
    __shared__ __align__(16) char sAh[128 * SMA];
    __shared__ __align__(16) char sAl[128 * SMA];
    __shared__ __align__(16) char sBh[128 * SMA];
    __shared__ __align__(16) char sBl[128 * SMA];

    int tid = threadIdx.x, lane = tid & 31, wid = tid >> 5;
    int m0 = blockIdx.y * 128, n0 = blockIdx.x * 128;
    int wm = (wid >> 1) * 32, wn = (wid & 1) * 64;
    int g = lane >> 2, q = lane & 3;

    float acc[2][8][4];
#pragma unroll
    for (int i = 0; i < 2; i++)
#pragma unroll
        for (int j = 0; j < 8; j++)
#pragma unroll
            for (int r = 0; r < 4; r++) acc[i][j][r] = 0.f;

    // stage-load roles: thread handles row tid/2, k-half tid&1 (16 elems)
    int arow = tid >> 1, half = tid & 1;
    bool avalid = (m0 + arow) < M;
    const float* aptr = A + (size_t)(m0 + arow) * lda + half * 16;
    const __nv_bfloat16* bhp = Wh + wbase + (size_t)(n0 + arow) * K + half * 16;
    const __nv_bfloat16* blp = Wl + wbase + (size_t)(n0 + arow) * K + half * 16;
    char* awh = sAh + arow * SMA + half * 32;
    char* awl = sAl + arow * SMA + half * 32;
    char* bwh = sBh + arow * SMA + half * 32;
    char* bwl = sBl + arow * SMA + half * 32;

    // ldmatrix lane address offsets
    uint32_t uAh = smem_u32(sAh), uAl = smem_u32(sAl);
    uint32_t uBh = smem_u32(sBh), uBl = smem_u32(sBl);
    int a_off = ((lane & 7) + ((lane >> 3) & 1) * 8) * SMA + (lane >> 4) * 16;
    int b_off = ((lane & 7) + (lane >> 4) * 8) * SMA + ((lane >> 3) & 1) * 16;
    uint32_t aAddrH0 = uAh + wm * SMA + a_off;
    uint32_t aAddrH1 = aAddrH0 + 16 * SMA;
    uint32_t aAddrL0 = uAl + wm * SMA + a_off;
    uint32_t aAddrL1 = aAddrL0 + 16 * SMA;
    uint32_t bAddrH = uBh + wn * SMA + b_off;
    uint32_t bAddrL = uBl + wn * SMA + b_off;

    for (int kt = 0; kt < K; kt += 32) {
        // ---- A: fp32 -> bf16 hi/lo split, 16 elems per thread ----
        {
            const float4* ap = reinterpret_cast<const float4*>(aptr + kt);
            float f[16];
#pragma unroll
            for (int i = 0; i < 4; i++) {
                float4 v = avalid ? ap[i] : make_float4(0.f, 0.f, 0.f, 0.f);
                f[i * 4 + 0] = v.x; f[i * 4 + 1] = v.y;
                f[i * 4 + 2] = v.z; f[i * 4 + 3] = v.w;
            }
            uint32_t hw[8], lw[8];
#pragma unroll
            for (int i = 0; i < 8; i++) {
                __nv_bfloat16 h0 = __float2bfloat16(f[2 * i]);
                __nv_bfloat16 h1 = __float2bfloat16(f[2 * i + 1]);
                __nv_bfloat16 l0 = __float2bfloat16(f[2 * i] - __bfloat162float(h0));
                __nv_bfloat16 l1 = __float2bfloat16(f[2 * i + 1] - __bfloat162float(h1));
                hw[i] = bf2u(h0, h1);
                lw[i] = bf2u(l0, l1);
            }
            *reinterpret_cast<uint4*>(awh)      = make_uint4(hw[0], hw[1], hw[2], hw[3]);
            *reinterpret_cast<uint4*>(awh + 16) = make_uint4(hw[4], hw[5], hw[6], hw[7]);
            *reinterpret_cast<uint4*>(awl)      = make_uint4(lw[0], lw[1], lw[2], lw[3]);
            *reinterpret_cast<uint4*>(awl + 16) = make_uint4(lw[4], lw[5], lw[6], lw[7]);
        }
        // ---- B: copy pre-split weights ----
        {
            const uint4* sh = reinterpret_cast<const uint4*>(bhp + kt);
            const uint4* sl = reinterpret_cast<const uint4*>(blp + kt);
            reinterpret_cast<uint4*>(bwh)[0] = sh[0];
            reinterpret_cast<uint4*>(bwh)[1] = sh[1];
            reinterpret_cast<uint4*>(bwl)[0] = sl[0];
            reinterpret_cast<uint4*>(bwl)[1] = sl[1];
        }
        __syncthreads();

#pragma unroll
        for (int ks = 0; ks < 2; ks++) {
            int kb = ks * 32;
            uint32_t ah[2][4], al[2][4];
            ldsm_x4(ah[0], aAddrH0 + kb);
            ldsm_x4(ah[1], aAddrH1 + kb);
            ldsm_x4(al[0], aAddrL0 + kb);
            ldsm_x4(al[1], aAddrL1 + kb);
#pragma unroll
            for (int p = 0; p < 4; p++) {
                uint32_t bh[4], bl[4];
                ldsm_x4(bh, bAddrH + p * 16 * SMA + kb);
                ldsm_x4(bl, bAddrL + p * 16 * SMA + kb);
#pragma unroll
                for (int mt = 0; mt < 2; mt++) {
                    mma_bf16(acc[mt][p * 2],     ah[mt], bh[0], bh[1]);
                    mma_bf16(acc[mt][p * 2],     ah[mt], bl[0], bl[1]);
                    mma_bf16(acc[mt][p * 2],     al[mt], bh[0], bh[1]);
                    mma_bf16(acc[mt][p * 2 + 1], ah[mt], bh[2], bh[3]);
                    mma_bf16(acc[mt][p * 2 + 1], ah[mt], bl[2], bl[3]);
                    mma_bf16(acc[mt][p * 2 + 1], al[mt], bh[2], bh[3]);
                }
            }
        }
        __syncthreads();
    }

    // ---- epilogue: regs -> global with bias/relu ----
#pragma unroll
    for (int nt = 0; nt < 8; nt++) {
        int c = n0 + wn + nt * 8 + q * 2;
        float b0 = bias ? bias[c]     : 0.f;
        float b1 = bias ? bias[c + 1] : 0.f;
#pragma unroll
        for (int mt = 0; mt < 2; mt++) {
            int r0 = m0 + wm + mt * 16 + g;
            int r1 = r0 + 8;
            float* a4 = acc[mt][nt];
            float2 lo = make_float2(a4[0] + b0, a4[1] + b1);
            float2 hi = make_float2(a4[2] + b0, a4[3] + b1);
            if (do_relu) {
                lo.x = fmaxf(lo.x, 0.f); lo.y = fmaxf(lo.y, 0.f);
                hi.x = fmaxf(hi.x, 0.f); hi.y = fmaxf(hi.y, 0.f);
            }
            if (r0 < M)
                *reinterpret_cast<float2*>(C + (size_t)r0 * ldc + c) = lo;
            if (r1 < M)
                *reinterpret_cast<float2*>(C + (size_t)r1 * ldc + c) = hi;
        }
    }
}

// ---------------- propagation: out = alpha*(L @ in) + beta*add + bias, relu -
__device__ __forceinline__ void accum4(float* acc, const float* p, float w) {
    float4 r = *reinterpret_cast<const float4*>(p);
    acc[0] = fmaf(w, r.x, acc[0]);
    acc[1] = fmaf(w, r.y, acc[1]);
    acc[2] = fmaf(w, r.z, acc[2]);
    acc[3] = fmaf(w, r.w, acc[3]);
}
__device__ __forceinline__ void accum2(float* acc, const float* p, float w) {
    float2 r = *reinterpret_cast<const float2*>(p);
    acc[0] = fmaf(w, r.x, acc[0]);
    acc[1] = fmaf(w, r.y, acc[1]);
}

template <int C>
__global__ __launch_bounds__(256) void prop_kernel(
    const float* __restrict__ in, int in_stride,
    float* __restrict__ out, int out_stride,
    const float* __restrict__ add, int add_stride,
    float alpha, float beta,
    const float* __restrict__ bias, int do_relu, int Nn)
{
    constexpr int V = C / 32;
    int gw = (blockIdx.x * blockDim.x + threadIdx.x) >> 5;
    int lane = threadIdx.x & 31;
    if (gw >= Nn) return;

    int start = g_rowstart[gw];
    int cnt = g_cnt[gw];
    float acc[V];
#pragma unroll
    for (int v = 0; v < V; v++) acc[v] = 0.f;

    const int feat = lane * V;
    int e = 0;
    for (; e + 4 <= cnt; e += 4) {
        int s0 = g_csr_src[start + e + 0];
        int s1 = g_csr_src[start + e + 1];
        int s2 = g_csr_src[start + e + 2];
        int s3 = g_csr_src[start + e + 3];
        float w0 = g_csr_w[start + e + 0];
        float w1 = g_csr_w[start + e + 1];
        float w2 = g_csr_w[start + e + 2];
        float w3 = g_csr_w[start + e + 3];
        const float* p0 = in + (size_t)s0 * in_stride + feat;
        const float* p1 = in + (size_t)s1 * in_stride + feat;
        const float* p2 = in + (size_t)s2 * in_stride + feat;
        const float* p3 = in + (size_t)s3 * in_stride + feat;
        if (V == 4) {
            accum4(acc, p0, w0); accum4(acc, p1, w1);
            accum4(acc, p2, w2); accum4(acc, p3, w3);
        } else {
            accum2(acc, p0, w0); accum2(acc, p1, w1);
            accum2(acc, p2, w2); accum2(acc, p3, w3);
        }
    }
    for (; e < cnt; e++) {
        int s = g_csr_src[start + e];
        float w = g_csr_w[start + e];
        const float* p = in + (size_t)s * in_stride + feat;
        if (V == 4) accum4(acc, p, w);
        else        accum2(acc, p, w);
    }

    float res[V];
#pragma unroll
    for (int v = 0; v < V; v++) res[v] = alpha * acc[v];
    if (add) {
        const float* ap = add + (size_t)gw * add_stride + feat;
        if (V == 4) {
            float4 a = *reinterpret_cast<const float4*>(ap);
            res[0] = fmaf(beta, a.x, res[0]);
            res[1] = fmaf(beta, a.y, res[1]);
            res[2] = fmaf(beta, a.z, res[2]);
            res[3] = fmaf(beta, a.w, res[3]);
        } else {
            float2 a = *reinterpret_cast<const float2*>(ap);
            res[0] = fmaf(beta, a.x, res[0]);
            res[1] = fmaf(beta, a.y, res[1]);
        }
    }
    if (bias) {
#pragma unroll
        for (int v = 0; v < V; v++) res[v] += bias[feat + v];
    }
    if (do_relu) {
#pragma unroll
        for (int v = 0; v < V; v++) res[v] = fmaxf(res[v], 0.f);
    }
    float* op = out + (size_t)gw * out_stride + feat;
    if (V == 4) {
        *reinterpret_cast<float4*>(op) = make_float4(res[0], res[1], res[2], res[3]);
    } else {
        *reinterpret_cast<float2*>(op) = make_float2(res[0], res[1]);
    }
}

// ---------------- launch ----------------------------------------------------
extern "C" void kernel_launch(void* const* d_in, const int* in_sizes, int n_in,
                              void* d_out, int out_size)
{
    const float* x  = (const float*)d_in[0];
    const void*  ei = d_in[1];
    const float* W1 = (const float*)d_in[3];
    const float* b1 = (const float*)d_in[4];
    const float* W2 = (const float*)d_in[5];
    const float* b2 = (const float*)d_in[6];
    const float* W3 = (const float*)d_in[7];
    const float* b3 = (const float*)d_in[8];

    int N = in_sizes[2];      // batch vector has N entries
    int E = in_sizes[1] / 2;

    float *Y, *U, *H2, *H3, *Wc;
    __nv_bfloat16 *Wth, *Wtl;
    cudaGetSymbolAddress((void**)&Y,   g_Y);
    cudaGetSymbolAddress((void**)&U,   g_U);
    cudaGetSymbolAddress((void**)&H2,  g_H2);
    cudaGetSymbolAddress((void**)&H3,  g_H3);
    cudaGetSymbolAddress((void**)&Wc,  g_Wcat);
    cudaGetSymbolAddress((void**)&Wth, g_Wth);
    cudaGetSymbolAddress((void**)&Wtl, g_Wtl);

    int nblk = (N + 255) / 256;
    int eblk = (E + 255) / 256;
    int nb1024 = (N + 1023) / 1024;
    int pblk = (N + 7) / 8;   // 8 warps / block
    int mgrid = (N + 127) / 128;

    // 1-5: setup + weight prep (so launch #6 = GEMM1 lands under ncu -s 5)
    init_kernel<<<nblk, 256>>>((const int*)ei, E, N);
    wcat_kernel<<<(128 * 256 + 255) / 256, 256>>>(W1, Wc);
    wprep_kernel<<<(256 * 128 + 255) / 256, 256>>>(Wc, 256, 128, 256, 0);
    wprep_kernel<<<(128 * 192 + 255) / 256, 256>>>(W2, 128, 192, 128, 32768);
    wprep_kernel<<<(256 * 384 + 255) / 256, 256>>>(W3, 256, 384, 256, 57344);

    // 6: GEMM1 — Y[:,0:256] = x @ Wcat (tensor cores, bf16x3)
    {
        dim3 g(2, mgrid);
        mma_gemm<<<g, 256>>>(x, 128, 128, Wth, Wtl, 0, Y, 256, N, nullptr, 0);
    }

    // graph build
    deg_cnt_kernel<<<eblk, 256>>>(ei, E);
    scan1_kernel<<<nb1024, 1024>>>(N);
    scan2_kernel<<<1, 256>>>(nb1024);
    scan3_kernel<<<nb1024, 1024>>>(N);
    fill_kernel<<<eblk, 256>>>(ei, E);

    // ---- layer 1 (output-space propagation):
    // out1 = relu( x(W0-W2) + L(xW1 + 2 L(xW2)) + b1 )
    // Y layout (stride 256): [y1 | y2 | y0 | pad]
    prop_kernel<64><<<pblk, 256>>>(Y + 64, 256, U, 64, Y, 256, 2.f, 1.f, nullptr, 0, N);
    prop_kernel<64><<<pblk, 256>>>(U, 64, H2, 192, Y + 128, 256, 1.f, 1.f, b1, 1, N);

    // ---- layer 2 ----
    prop_kernel<64><<<pblk, 256>>>(H2, 192, H2 + 64, 192, nullptr, 0, 1.f, 0.f, nullptr, 0, N);
    prop_kernel<64><<<pblk, 256>>>(H2 + 64, 192, H2 + 128, 192, H2, 192, 2.f, -1.f, nullptr, 0, N);
    {
        dim3 g(1, mgrid);
        mma_gemm<<<g, 256>>>(H2, 192, 192, Wth, Wtl, 32768, H3, 384, N, b2, 1);
    }

    // ---- layer 3 ----
    prop_kernel<128><<<pblk, 256>>>(H3, 384, H3 + 128, 384, nullptr, 0, 1.f, 0.f, nullptr, 0, N);
    prop_kernel<128><<<pblk, 256>>>(H3 + 128, 384, H3 + 256, 384, H3, 384, 2.f, -1.f, nullptr, 0, N);
    {
        dim3 g(2, mgrid);
        mma_gemm<<<g, 256>>>(H3, 384, 384, Wth, Wtl, 57344, (float*)d_out, 256, N, b3, 0);
    }
}